// round 16
// baseline (speedup 1.0000x reference)
#include <cuda_runtime.h>
#include <math.h>
#include <stdint.h>

// ---------------------------------------------------------------------------
// Multi-scale region distillation loss — single kernel, cp.async pipeline +
// L2 BULK PREFETCH.
//
// R16: five load engines (LDG scalar/vector, cp.async block/warp, TMA bulk)
// all cap at 3.8-3.9TB/s with DRAM cycles-active only 48% -> shared
// latency x miss-slot-concurrency limit on the DEMAND-miss path.
// cp.async.bulk.prefetch.L2 is fire-and-forget DRAM->L2 (no completion
// tracking, no SM-side slots): prefetch 8 groups (64KB/block, ~43MB chip-wide,
// fits L2) ahead, turning demand cp.async loads into ~250cyc L2 hits.
//
// Base geometry = R13 best (94.3us): block = 256px x 256ch, 4-stage ring,
// stage = 4 channels (f 4KB + fo 4KB), block-wide wait_group+syncthreads.
// ---------------------------------------------------------------------------

#define NUM_SCALES 4
#define MAXC 32
#define LAB_DIM 512
#define THREADS 256
#define PXB 256                 // pixels per block/chunk
#define STAGES 4
#define CPS 4                   // channels per stage
#define STAGE_FLOATS (CPS * PXB * 2)   // 2048 floats = 8KB
#define PF_AHEAD 8              // prefetch distance in channel groups

__device__ double       g_seg[NUM_SCALES * MAXC];   // zero-init at load
__device__ float        g_cnt[NUM_SCALES * MAXC];   // zero-init at load
__device__ unsigned int g_blocks_done = 0;          // zero-init at load

struct ScaleDesc {
    const float* f;
    const float* fo;
    int C;           // channels
    int W;           // spatial width (=H)
    int HW;          // H*W
    int block_base;  // first block of this scale
    int sub;         // LAB_DIM / H
};
struct AllDesc { ScaleDesc s[NUM_SCALES]; };

__device__ __forceinline__ void cp16(uint32_t dst, const void* src) {
    asm volatile("cp.async.cg.shared.global [%0], [%1], 16;"
                 :: "r"(dst), "l"(src) : "memory");
}
__device__ __forceinline__ void cp_commit() {
    asm volatile("cp.async.commit_group;" ::: "memory");
}
__device__ __forceinline__ void cp_wait2() {
    asm volatile("cp.async.wait_group 2;" ::: "memory");
}
__device__ __forceinline__ void l2_prefetch(const void* src, uint32_t bytes) {
    asm volatile("cp.async.bulk.prefetch.L2.global [%0], %1;"
                 :: "l"(src), "r"(bytes) : "memory");
}

__global__ void __launch_bounds__(THREADS, 5)
msrd_kernel(AllDesc d, const int* __restrict__ lab,
            const int* __restrict__ ncls_p, const int* __restrict__ nold_p,
            float* __restrict__ out)
{
    __shared__ float s_tile[STAGES][STAGE_FLOATS];   // 32KB
    __shared__ float s_seg[MAXC];
    __shared__ float s_cnt[MAXC];
    __shared__ int   s_is_last;

    const int t = (int)threadIdx.x;
    if (t < MAXC) { s_seg[t] = 0.f; s_cnt[t] = 0.f; }

    int sidx;
    if      ((int)blockIdx.x < d.s[1].block_base) sidx = 0;
    else if ((int)blockIdx.x < d.s[2].block_base) sidx = 1;
    else if ((int)blockIdx.x < d.s[3].block_base) sidx = 2;
    else                                          sidx = 3;
    const ScaleDesc sd = d.s[sidx];

    const int chunk = (int)blockIdx.x - sd.block_base;
    const int px0   = chunk * PXB;               // pixel offset within scale
    const int b     = px0 / sd.HW;               // PXB divides HW
    const int p0    = px0 - b * sd.HW;
    const int HW    = sd.HW;
    const int C     = sd.C;
    const int ngrp  = C / CPS;                   // 64 channel groups

    const float* __restrict__ fA = sd.f  + (size_t)b * C * HW + p0;
    const float* __restrict__ fO = sd.fo + (size_t)b * C * HW + p0;

    // cp.async thread mapping: thread t covers channel (t>>6) of the stage,
    // 16B part (t&63) of that 1KB channel row.
    const float* srcA0 = fA + (size_t)(t >> 6) * HW + (t & 63) * 4;
    const float* srcO0 = fO + (size_t)(t >> 6) * HW + (t & 63) * 4;
    const size_t grp_stride = (size_t)CPS * HW;  // floats per channel group

    const uint32_t tile_u32 =
        (uint32_t)__cvta_generic_to_shared(&s_tile[0][0]);
    const uint32_t dstA = (uint32_t)(t * 16);          // f region [0,4096)
    const uint32_t dstO = (uint32_t)(4096 + t * 16);   // fo region [4096,8192)

    // Prefetch thread mapping: threads 0..7 -> 1KB row each per group.
    //   t<4:  f  channel row t;  4<=t<8: fo channel row t-4.
    const bool  pf_en  = (t < 8);
    const float* pfbase = (t < 4) ? (fA + (size_t)t * HW)
                                  : (fO + (size_t)(t - 4) * HW);

    // ---------------- L2 prefetch prologue: groups 0..PF_AHEAD-1 -----------
    if (pf_en) {
        #pragma unroll
        for (int g = 0; g < PF_AHEAD; ++g)
            l2_prefetch(pfbase + (size_t)g * grp_stride, PXB * 4);
    }

    // ---------------- cp.async pipeline prologue: groups 0..2 --------------
    #pragma unroll
    for (int g = 0; g < STAGES - 1; ++g) {
        const uint32_t sb = tile_u32 + (uint32_t)g * (STAGE_FLOATS * 4);
        cp16(sb + dstA, srcA0 + (size_t)g * grp_stride);
        cp16(sb + dstO, srcO0 + (size_t)g * grp_stride);
        cp_commit();
    }

    // ---------------- main loop over channel groups ----------------
    float dot = 0.f, na = 0.f, nb = 0.f;
    #pragma unroll 1
    for (int g = 0; g < ngrp; ++g) {
        // keep the L2 prefetch front PF_AHEAD groups ahead of consumption
        const int gp = g + PF_AHEAD;
        if (pf_en && gp < ngrp)
            l2_prefetch(pfbase + (size_t)gp * grp_stride, PXB * 4);

        cp_wait2();          // group g landed (<=2 groups outstanding)
        __syncthreads();

        const int sl = g & (STAGES - 1);
        const float* __restrict__ fa  = &s_tile[sl][0];
        const float* __restrict__ fo2 = &s_tile[sl][CPS * PXB];
        #pragma unroll
        for (int c = 0; c < CPS; ++c) {
            const float a = fa [c * PXB + t];
            const float o = fo2[c * PXB + t];
            dot = fmaf(a, o, dot);
            na  = fmaf(a, a, na);
            nb  = fmaf(o, o, nb);
        }

        // refill slot (g+3)&3 == (g-1)&3: consumed by all threads before the
        // barrier above. Safe to overwrite.
        const int gn = g + STAGES - 1;
        if (gn < ngrp) {
            const uint32_t sb = tile_u32 + (uint32_t)(gn & (STAGES - 1))
                                           * (STAGE_FLOATS * 4);
            cp16(sb + dstA, srcA0 + (size_t)gn * grp_stride);
            cp16(sb + dstO, srcO0 + (size_t)gn * grp_stride);
        }
        cp_commit();
    }

    // ---------------- per-pixel epilogue ----------------
    {
        const float nf  = fmaxf(sqrtf(na), 1e-8f);
        const float nfo = fmaxf(sqrtf(nb), 1e-8f);
        const float sim = dot / (nf * nfo);

        const int p = p0 + t;
        const int h = p / sd.W;
        const int w = p - h * sd.W;
        const int l = lab[(size_t)b * LAB_DIM * LAB_DIM
                          + (size_t)(h * sd.sub) * LAB_DIM + (size_t)w * sd.sub];
        if (l >= 0 && l < MAXC) {
            atomicAdd(&s_seg[l], sim);
            atomicAdd(&s_cnt[l], 1.0f);
        }
    }

    __syncthreads();
    if (t < MAXC) {
        const float cs = s_cnt[t];
        if (cs != 0.0f) {
            atomicAdd(&g_seg[sidx * MAXC + t], (double)s_seg[t]);
            atomicAdd(&g_cnt[sidx * MAXC + t], cs);
        }
    }

    // ---------------- last-block finalize ----------------
    __syncthreads();
    if (t == 0) {
        __threadfence();
        const unsigned int done = atomicAdd(&g_blocks_done, 1u);
        s_is_last = (done == gridDim.x - 1) ? 1 : 0;
    }
    __syncthreads();
    if (!s_is_last) return;

    __threadfence();
    if (t == 0) {
        const int nc = ncls_p ? *ncls_p : 21;
        const int no = nold_p ? *nold_p : 15;
        const double wts[NUM_SCALES] = {1.0, 2.0, 3.0, 4.0};
        double loss = 0.0;
        for (int s = 0; s < NUM_SCALES; ++s) {
            for (int cls = 0; cls < nc && cls < MAXC; ++cls) {
                const float cnt = g_cnt[s * MAXC + cls];
                if (cnt > 0.0f) {
                    const double mean = g_seg[s * MAXC + cls] / (double)cnt;
                    double factor;
                    if (cls == 0)        factor = (double)no / (double)nc;
                    else if (cls <= no)  factor = 1.0;
                    else                 factor = 0.0;
                    loss += wts[s] * factor * (1.0 - mean);
                }
            }
        }
        *out = (float)loss;
    }

    __syncthreads();   // loss read complete before resets
    if (t == 0) g_blocks_done = 0;
    if (t < NUM_SCALES * MAXC / 2) {
        const int r = t * 2;
        g_seg[r] = 0.0;  g_seg[r + 1] = 0.0;
        g_cnt[r] = 0.0f; g_cnt[r + 1] = 0.0f;
    }
}

extern "C" void kernel_launch(void* const* d_in, const int* in_sizes, int n_in,
                              void* d_out, int out_size)
{
    const int* lab = (const int*)d_in[0];
    const int B = in_sizes[0] / (LAB_DIM * LAB_DIM);

    // ---- identify feature buffers by size (order-agnostic) ----
    const float* fbuf[NUM_SCALES]  = {nullptr, nullptr, nullptr, nullptr};
    const float* fobuf[NUM_SCALES] = {nullptr, nullptr, nullptr, nullptr};
    long         szs[NUM_SCALES]   = {0, 0, 0, 0};
    int ns = 0;
    const int* scalar_ptrs[2] = {nullptr, nullptr};
    int nscalar = 0;

    for (int i = 1; i < n_in; ++i) {
        const long sz = in_sizes[i];
        if (sz <= 1) {
            if (nscalar < 2) scalar_ptrs[nscalar++] = (const int*)d_in[i];
            continue;
        }
        int j = 0;
        while (j < ns && szs[j] != sz) ++j;
        if (j == ns && ns < NUM_SCALES) {
            szs[ns] = sz; fbuf[ns] = (const float*)d_in[i]; ++ns;
        } else if (j < ns) {
            fobuf[j] = (const float*)d_in[i];
        }
    }
    for (int i = 0; i < ns; ++i)
        for (int j = i + 1; j < ns; ++j)
            if (szs[j] > szs[i]) {
                long ts = szs[i]; szs[i] = szs[j]; szs[j] = ts;
                const float* tf = fbuf[i]; fbuf[i] = fbuf[j]; fbuf[j] = tf;
                const float* to = fobuf[i]; fobuf[i] = fobuf[j]; fobuf[j] = to;
            }

    // ---- per-scale descriptors (uniform 256-px chunks) ----
    AllDesc ad;
    int block_base = 0;
    for (int s = 0; s < NUM_SCALES; ++s) {
        const int HW_dim = 128 >> s;             // 128,64,32,16
        const int HW     = HW_dim * HW_dim;
        const int C      = (int)(szs[s] / ((long)B * HW));
        const int pixels = B * HW;
        const int nblk   = pixels / PXB;

        ad.s[s].f          = fbuf[s];
        ad.s[s].fo         = fobuf[s];
        ad.s[s].C          = C;
        ad.s[s].W          = HW_dim;
        ad.s[s].HW         = HW;
        ad.s[s].block_base = block_base;
        ad.s[s].sub        = LAB_DIM / HW_dim;
        block_base += nblk;
    }

    msrd_kernel<<<block_base, THREADS>>>(ad, lab,
                                         scalar_ptrs[0], scalar_ptrs[1],
                                         (float*)d_out);
}